// round 5
// baseline (speedup 1.0000x reference)
#include <cuda_runtime.h>
#include <stdint.h>

// Problem constants (fixed for this dataset variant)
#define NN       196608     // nodes
#define FD       64         // feature dim (F_IN == F_OUT)
#define NH       9          // neighbors per node
#define NODES_PB 128        // nodes per block in layer kernel
#define LN_EPS   1e-5f

// Scratch (device globals: allocation-free rule)
__device__ float g_h1[(size_t)NN * FD];
__device__ float g_h2[(size_t)NN * FD];

// ---------------------------------------------------------------------------
// Kernel 1: h1 = silu(layernorm(x))   — one warp per row, float2 per lane
// ---------------------------------------------------------------------------
__global__ void k_ln_silu(const float* __restrict__ x,
                          const float* __restrict__ lnw,
                          const float* __restrict__ lnb) {
    int row  = (blockIdx.x * blockDim.x + threadIdx.x) >> 5;
    int lane = threadIdx.x & 31;
    if (row >= NN) return;

    float2 v = ((const float2*)(x + (size_t)row * FD))[lane];

    float s = v.x + v.y;
    #pragma unroll
    for (int o = 16; o; o >>= 1) s += __shfl_xor_sync(0xffffffffu, s, o);
    float mu = s * (1.0f / FD);

    float dx = v.x - mu, dy = v.y - mu;
    float q = dx * dx + dy * dy;
    #pragma unroll
    for (int o = 16; o; o >>= 1) q += __shfl_xor_sync(0xffffffffu, q, o);
    float rs = rsqrtf(q * (1.0f / FD) + LN_EPS);

    float2 wv = ((const float2*)lnw)[lane];
    float2 bv = ((const float2*)lnb)[lane];
    float a0 = dx * rs * wv.x + bv.x;
    float a1 = dy * rs * wv.y + bv.y;
    a0 = a0 / (1.0f + __expf(-a0));
    a1 = a1 / (1.0f + __expf(-a1));

    ((float2*)(g_h1 + (size_t)row * FD))[lane] = make_float2(a0, a1);
}

// ---------------------------------------------------------------------------
// Layer kernel: y[n,o] = b[o] + sum_k sum_f h_in[adj[n,k]][f] * W[k][f][o]
//   FINAL==false: h2 = silu(LN(y))  (writes g_h2)
//   FINAL==true : out = y + x_res   (writes out)
// Block: 256 threads, 128 nodes. Per head: stage W_k (64x64) + gathered tile
// sH[f][node] (64x128, f-major) in smem; compute with packed f32x2 FMAs:
// warp owns 16 nodes (as 8 node-pairs), lane owns cols {lane, lane+32}.
// ---------------------------------------------------------------------------
#define SM_W_FLOATS   (FD * FD)          // 4096
#define SM_H_FLOATS   (FD * NODES_PB)    // 8192
#define SM_IDX_INTS   (NODES_PB * NH)    // 1152
#define SMEM_BYTES    ((SM_W_FLOATS + SM_H_FLOATS) * 4 + SM_IDX_INTS * 4)  // 53760

template <bool FINAL>
__global__ __launch_bounds__(256) void k_layer(
    const float* __restrict__ hin,        // gathered source (g_h1 or g_h2)
    const int* __restrict__ adjc,         // [NN][NH] int32 (harness dtype set)
    const float* __restrict__ W,          // [NH][FD][FD]
    const float* __restrict__ bias,       // [FD]
    const float* __restrict__ lnw,        // ln weights (FINAL: unused)
    const float* __restrict__ lnb,
    const float* __restrict__ xres,       // residual (only FINAL)
    float* __restrict__ outp)             // g_h2 or d_out
{
    extern __shared__ float smem[];
    float* sW   = smem;                       // [64][64]
    float* sH   = smem + SM_W_FLOATS;         // [64][128] f-major
    int*   sIdx = (int*)(smem + SM_W_FLOATS + SM_H_FLOATS); // [128][9]

    const int tid   = threadIdx.x;
    const int lane  = tid & 31;
    const int warp  = tid >> 5;
    const int node0 = blockIdx.x * NODES_PB;

    // Stage neighbor indices for this block (clamped: OOB -> wrong answer,
    // never a crash — keeps failures diagnosable)
    for (int i = tid; i < NODES_PB * NH; i += 256) {
        int v = adjc[(size_t)node0 * NH + i];
        v = (v < 0) ? 0 : ((v >= NN) ? NN - 1 : v);
        sIdx[i] = v;
    }

    unsigned long long acc[16];
    #pragma unroll
    for (int i = 0; i < 16; ++i) acc[i] = 0ull;

    const int gn = tid & (NODES_PB - 1);   // gather: node within block
    const int fb = (tid >> 7) * 32;        // gather: f half (0 or 32)

    for (int k = 0; k < NH; ++k) {
        __syncthreads();  // (also covers sIdx on first iteration)

        // Stage W_k: contiguous 16KB copy
        {
            const float4* Wk  = (const float4*)(W + (size_t)k * FD * FD);
            float4*       sW4 = (float4*)sW;
            #pragma unroll
            for (int i = 0; i < 4; ++i) sW4[tid + 256 * i] = Wk[tid + 256 * i];
        }
        // Gather: 2 threads per node, each moves 32 floats, transpose into sH[f][node]
        {
            int src = sIdx[gn * NH + k];
            const float4* hp = (const float4*)(hin + (size_t)src * FD + fb);
            #pragma unroll
            for (int i = 0; i < 8; ++i) {
                float4 v = hp[i];
                int f = fb + i * 4;
                sH[(f + 0) * NODES_PB + gn] = v.x;
                sH[(f + 1) * NODES_PB + gn] = v.y;
                sH[(f + 2) * NODES_PB + gn] = v.z;
                sH[(f + 3) * NODES_PB + gn] = v.w;
            }
        }
        __syncthreads();

        // Compute: warp -> nodes [warp*16, warp*16+16), lane -> cols {lane, lane+32}
        #pragma unroll 2
        for (int f = 0; f < FD; ++f) {
            float wa = sW[f * FD + lane];
            float wb = sW[f * FD + lane + 32];
            unsigned long long w2a, w2b;
            asm("mov.b64 %0, {%1, %1};" : "=l"(w2a) : "f"(wa));
            asm("mov.b64 %0, {%1, %1};" : "=l"(w2b) : "f"(wb));
            const unsigned long long* xp =
                (const unsigned long long*)(sH + f * NODES_PB) + warp * 8;
            #pragma unroll
            for (int p = 0; p < 8; ++p) {
                unsigned long long x2 = xp[p];  // (node 2p, node 2p+1) broadcast
                asm("fma.rn.f32x2 %0, %1, %2, %0;"
                    : "+l"(acc[2 * p])     : "l"(x2), "l"(w2a));
                asm("fma.rn.f32x2 %0, %1, %2, %0;"
                    : "+l"(acc[2 * p + 1]) : "l"(x2), "l"(w2b));
            }
        }
    }

    const float bl = bias[lane];
    const float bh = bias[lane + 32];

    if (FINAL) {
        // out = y + b + x_res  (coalesced 128B stores per row-half)
        #pragma unroll
        for (int p = 0; p < 8; ++p) {
            float2 a = *(float2*)&acc[2 * p];       // (.x: node 2p, .y: node 2p+1) @ col lane
            float2 c = *(float2*)&acc[2 * p + 1];   // same @ col lane+32
            size_t n0 = (size_t)(node0 + warp * 16 + 2 * p) * FD;
            size_t n1 = n0 + FD;
            outp[n0 + lane]      = a.x + bl + xres[n0 + lane];
            outp[n0 + lane + 32] = c.x + bh + xres[n0 + lane + 32];
            outp[n1 + lane]      = a.y + bl + xres[n1 + lane];
            outp[n1 + lane + 32] = c.y + bh + xres[n1 + lane + 32];
        }
    } else {
        // Stage y+b into smem (node-major), then LN+SiLU per node
        __syncthreads();
        float* sY = sH;  // [128][64]
        #pragma unroll
        for (int p = 0; p < 8; ++p) {
            float2 a = *(float2*)&acc[2 * p];
            float2 c = *(float2*)&acc[2 * p + 1];
            int nl0 = warp * 16 + 2 * p;
            sY[nl0 * FD + lane]            = a.x + bl;
            sY[nl0 * FD + lane + 32]       = c.x + bh;
            sY[(nl0 + 1) * FD + lane]      = a.y + bl;
            sY[(nl0 + 1) * FD + lane + 32] = c.y + bh;
        }
        __syncthreads();

        float2 wv = ((const float2*)lnw)[lane];
        float2 bv = ((const float2*)lnb)[lane];
        for (int i = 0; i < 16; ++i) {
            int nl = warp * 16 + i;
            float2 v = ((const float2*)(sY + nl * FD))[lane];
            float s = v.x + v.y;
            #pragma unroll
            for (int o = 16; o; o >>= 1) s += __shfl_xor_sync(0xffffffffu, s, o);
            float mu = s * (1.0f / FD);
            float dx = v.x - mu, dy = v.y - mu;
            float q = dx * dx + dy * dy;
            #pragma unroll
            for (int o = 16; o; o >>= 1) q += __shfl_xor_sync(0xffffffffu, q, o);
            float rs = rsqrtf(q * (1.0f / FD) + LN_EPS);
            float a0 = dx * rs * wv.x + bv.x;
            float a1 = dy * rs * wv.y + bv.y;
            a0 = a0 / (1.0f + __expf(-a0));
            a1 = a1 / (1.0f + __expf(-a1));
            ((float2*)(outp + (size_t)(node0 + nl) * FD))[lane] = make_float2(a0, a1);
        }
    }
}

// ---------------------------------------------------------------------------
extern "C" void kernel_launch(void* const* d_in, const int* in_sizes, int n_in,
                              void* d_out, int out_size) {
    const float* x    = (const float*)d_in[0];
    const int*   adjc = (const int*)d_in[1];     // int32 (harness dtype set)
    const float* ln1w = (const float*)d_in[2];
    const float* ln1b = (const float*)d_in[3];
    const float* W1   = (const float*)d_in[4];
    const float* b1   = (const float*)d_in[5];
    const float* ln2w = (const float*)d_in[6];
    const float* ln2b = (const float*)d_in[7];
    const float* W2   = (const float*)d_in[8];
    const float* b2   = (const float*)d_in[9];
    float*       out  = (float*)d_out;

    (void)in_sizes; (void)n_in; (void)out_size;

    // Dynamic smem opt-in (53760B > default 48KB). Host-side attribute set is
    // not a stream op — safe under graph capture; idempotent per call.
    cudaFuncSetAttribute(k_layer<false>,
                         cudaFuncAttributeMaxDynamicSharedMemorySize, SMEM_BYTES);
    cudaFuncSetAttribute(k_layer<true>,
                         cudaFuncAttributeMaxDynamicSharedMemorySize, SMEM_BYTES);

    float* h1p; cudaGetSymbolAddress((void**)&h1p, g_h1);
    float* h2p; cudaGetSymbolAddress((void**)&h2p, g_h2);

    // K1: h1 = silu(LN(x))
    k_ln_silu<<<NN / 8, 256>>>(x, ln1w, ln1b);

    // K2: h2 = silu(LN(gather(h1) @ W1 + b1))
    k_layer<false><<<NN / NODES_PB, 256, SMEM_BYTES>>>(
        h1p, adjc, W1, b1, ln2w, ln2b, nullptr, h2p);

    // K3: out = gather(h2) @ W2 + b2 + x
    k_layer<true><<<NN / NODES_PB, 256, SMEM_BYTES>>>(
        h2p, adjc, W2, b2, nullptr, nullptr, x, out);
}

// round 9
// speedup vs baseline: 1.6420x; 1.6420x over previous
#include <cuda_runtime.h>
#include <cuda_bf16.h>
#include <stdint.h>

// Problem constants
#define NN       196608
#define FD       64
#define NH       9
#define LN_EPS   1e-5f

// Split bf16 activations (hi + lo ~= fp32 to ~16 mantissa bits)
__device__ __align__(256) __nv_bfloat16 g_hi1[(size_t)NN * FD];
__device__ __align__(256) __nv_bfloat16 g_lo1[(size_t)NN * FD];
__device__ __align__(256) __nv_bfloat16 g_hi2[(size_t)NN * FD];
__device__ __align__(256) __nv_bfloat16 g_lo2[(size_t)NN * FD];

// ---------------------------------------------------------------------------
// Helpers (sm_80-level features only: ldmatrix + mma.sync — legal on sm_103 base)
// ---------------------------------------------------------------------------
__device__ __forceinline__ uint32_t smem_u32(const void* p) {
    uint32_t a;
    asm("{ .reg .u64 t; cvta.to.shared.u64 t, %1; cvt.u32.u64 %0, t; }"
        : "=r"(a) : "l"(p));
    return a;
}

__device__ __forceinline__ void ldsm_x4(uint32_t& r0, uint32_t& r1,
                                        uint32_t& r2, uint32_t& r3, uint32_t a) {
    asm volatile("ldmatrix.sync.aligned.m8n8.x4.shared.b16 {%0,%1,%2,%3}, [%4];"
                 : "=r"(r0), "=r"(r1), "=r"(r2), "=r"(r3) : "r"(a));
}
__device__ __forceinline__ void ldsm_x4_t(uint32_t& r0, uint32_t& r1,
                                          uint32_t& r2, uint32_t& r3, uint32_t a) {
    asm volatile("ldmatrix.sync.aligned.m8n8.x4.trans.shared.b16 {%0,%1,%2,%3}, [%4];"
                 : "=r"(r0), "=r"(r1), "=r"(r2), "=r"(r3) : "r"(a));
}
__device__ __forceinline__ void mma_bf16(float* c, const uint32_t* a,
                                         uint32_t b0, uint32_t b1) {
    asm volatile(
        "mma.sync.aligned.m16n8k16.row.col.f32.bf16.bf16.f32 "
        "{%0,%1,%2,%3}, {%4,%5,%6,%7}, {%8,%9}, {%0,%1,%2,%3};"
        : "+f"(c[0]), "+f"(c[1]), "+f"(c[2]), "+f"(c[3])
        : "r"(a[0]), "r"(a[1]), "r"(a[2]), "r"(a[3]), "r"(b0), "r"(b1));
}

__device__ __forceinline__ unsigned pack2(__nv_bfloat16 a, __nv_bfloat16 b) {
    return (unsigned)__bfloat16_as_ushort(a) | ((unsigned)__bfloat16_as_ushort(b) << 16);
}
__device__ __forceinline__ void split1(float v, __nv_bfloat16& h, __nv_bfloat16& l) {
    h = __float2bfloat16(v);
    l = __float2bfloat16(v - __bfloat162float(h));
}

// ---------------------------------------------------------------------------
// Kernel 1: (hi1, lo1) = split(silu(layernorm(x)))
// ---------------------------------------------------------------------------
__global__ void k_ln_silu(const float* __restrict__ x,
                          const float* __restrict__ lnw,
                          const float* __restrict__ lnb) {
    int row  = (blockIdx.x * blockDim.x + threadIdx.x) >> 5;
    int lane = threadIdx.x & 31;
    if (row >= NN) return;

    float2 v = ((const float2*)(x + (size_t)row * FD))[lane];

    float s = v.x + v.y;
    #pragma unroll
    for (int o = 16; o; o >>= 1) s += __shfl_xor_sync(0xffffffffu, s, o);
    float mu = s * (1.0f / FD);

    float dx = v.x - mu, dy = v.y - mu;
    float q = dx * dx + dy * dy;
    #pragma unroll
    for (int o = 16; o; o >>= 1) q += __shfl_xor_sync(0xffffffffu, q, o);
    float rs = rsqrtf(q * (1.0f / FD) + LN_EPS);

    float2 wv = ((const float2*)lnw)[lane];
    float2 bv = ((const float2*)lnb)[lane];
    float a0 = dx * rs * wv.x + bv.x;
    float a1 = dy * rs * wv.y + bv.y;
    a0 = a0 / (1.0f + __expf(-a0));
    a1 = a1 / (1.0f + __expf(-a1));

    __nv_bfloat16 h0, l0, h1, l1;
    split1(a0, h0, l0);
    split1(a1, h1, l1);
    ((unsigned*)g_hi1)[(size_t)row * 32 + lane] = pack2(h0, h1);
    ((unsigned*)g_lo1)[(size_t)row * 32 + lane] = pack2(l0, l1);
}

// ---------------------------------------------------------------------------
// Layer kernel: warp-level bf16 MMA, 2-term split, fp32 accumulators.
// Block = 256 threads / 128 nodes; warp w -> nodes [16w, 16w+16).
// Smem tiles (16B-chunk XOR swizzle, conflict-free ldmatrix):
//   A hi/lo: 128 rows x 128B  (gathered node features, k-major)
//   B hi/lo:  64 rows x 128B  (W_k as-is, [f][o]; B fragment via ldmatrix.trans)
// Per head: 96 mma.sync per warp (3 split-terms x 4 k-steps x 8 n-tiles).
// ---------------------------------------------------------------------------
#define SM_A_HI   0
#define SM_A_LO   16384
#define SM_B_HI   32768
#define SM_B_LO   40960
#define SM_IDX    49152               // 1152 ints
#define SM_BIAS   (49152 + 4608)      // 64 floats
#define SMEM_TOTAL (SM_BIAS + 256 + 256)

template <bool FINAL>
__global__ __launch_bounds__(256) void k_layer(
    const __nv_bfloat16* __restrict__ hin_hi,
    const __nv_bfloat16* __restrict__ hin_lo,
    const int* __restrict__ adjc,
    const float* __restrict__ W,      // [NH][FD][FD]  (f-major rows, o cols)
    const float* __restrict__ bias,
    const float* __restrict__ lnw,
    const float* __restrict__ lnb,
    const float* __restrict__ xres,
    __nv_bfloat16* __restrict__ out_hi,
    __nv_bfloat16* __restrict__ out_lo,
    float* __restrict__ outp)
{
    extern __shared__ char smem[];
    const uint32_t sb = smem_u32(smem);
    const int tid  = threadIdx.x;
    const int lane = tid & 31;
    const int warp = tid >> 5;
    const int node0 = blockIdx.x * 128;

    int*   sIdx  = (int*)(smem + SM_IDX);
    float* sBias = (float*)(smem + SM_BIAS);

    if (tid < 64) sBias[tid] = bias[tid];
    for (int i = tid; i < 128 * NH; i += 256) {
        int v = adjc[(size_t)node0 * NH + i];
        v = (v < 0) ? 0 : ((v >= NN) ? NN - 1 : v);
        sIdx[i] = v;
    }

    float acc[32];                    // 8 n-tiles x {c0,c1,c2,c3}
    #pragma unroll
    for (int i = 0; i < 32; ++i) acc[i] = 0.0f;

    const int gnode = tid & 127;      // gather: node within block
    const int gsel  = tid >> 7;       // 0 = hi tile, 1 = lo tile
    const int l7    = lane & 7;
    const int l15   = lane & 15;
    const int hi16  = lane >> 4;      // A: k-chunk select
    const int g8    = lane >> 3;      // B: tile group

    // A fragment row (constant across heads/k-steps): r & 7 == lane & 7
    const uint32_t a_row_off = (uint32_t)(16 * warp + l15) * 128;
    // B: k-row within a k-step: 8*(g&1) + l7 ; chunk xor uses (krow&7) == l7
    const uint32_t b_krow_off = (uint32_t)(8 * (g8 & 1) + l7) * 128;
    const int b_cg = g8 >> 1;         // B: n-pair half select

    for (int k = 0; k < NH; ++k) {
        __syncthreads();              // prior compute done (covers sIdx, 1st iter)

        // ---- Stage A (gather): 16B chunks, chunk c stored at c ^ (row&7) ----
        {
            int src = sIdx[gnode * NH + k];
            const uint4* row = (const uint4*)((gsel ? hin_lo : hin_hi) + (size_t)src * FD);
            char* dst = smem + (gsel ? SM_A_LO : SM_A_HI) + gnode * 128;
            #pragma unroll
            for (int c = 0; c < 8; ++c)
                *(uint4*)(dst + (((c ^ (gnode & 7)) << 4))) = row[c];
        }
        // ---- Stage B: W_k fp32 -> split bf16 hi/lo, k-major, swizzled ----
        {
            #pragma unroll
            for (int it = 0; it < 2; ++it) {
                int ch = tid + 256 * it;          // 512 chunks: (f, 16B chunk)
                int f = ch >> 3, c = ch & 7;
                const float4* wp = (const float4*)(W + (size_t)k * 4096 + f * 64 + c * 8);
                float4 v0 = wp[0], v1 = wp[1];
                float vv[8] = {v0.x, v0.y, v0.z, v0.w, v1.x, v1.y, v1.z, v1.w};
                unsigned rh[4], rl[4];
                #pragma unroll
                for (int j = 0; j < 4; ++j) {
                    __nv_bfloat16 h0, l0, h1, l1;
                    split1(vv[2 * j], h0, l0);
                    split1(vv[2 * j + 1], h1, l1);
                    rh[j] = pack2(h0, h1);
                    rl[j] = pack2(l0, l1);
                }
                uint32_t off = (uint32_t)f * 128 + (((c ^ (f & 7)) << 4));
                *(uint4*)(smem + SM_B_HI + off) = make_uint4(rh[0], rh[1], rh[2], rh[3]);
                *(uint4*)(smem + SM_B_LO + off) = make_uint4(rl[0], rl[1], rl[2], rl[3]);
            }
        }
        __syncthreads();

        // ---- Compute: 4 k-steps x (A-frags + 4 n-pairs) ----
        #pragma unroll
        for (int ks = 0; ks < 4; ++ks) {
            uint32_t a_chunk_off = (uint32_t)(((2 * ks + hi16) ^ l7) << 4);
            uint32_t ah[4], al[4];
            ldsm_x4(ah[0], ah[1], ah[2], ah[3], sb + SM_A_HI + a_row_off + a_chunk_off);
            ldsm_x4(al[0], al[1], al[2], al[3], sb + SM_A_LO + a_row_off + a_chunk_off);

            uint32_t b_row = (uint32_t)(16 * ks) * 128 + b_krow_off;
            #pragma unroll
            for (int p = 0; p < 4; ++p) {
                uint32_t b_chunk_off = (uint32_t)((((2 * p + b_cg)) ^ l7) << 4);
                uint32_t bh0, bh1, bh2, bh3, bl0, bl1, bl2, bl3;
                ldsm_x4_t(bh0, bh1, bh2, bh3, sb + SM_B_HI + b_row + b_chunk_off);
                ldsm_x4_t(bl0, bl1, bl2, bl3, sb + SM_B_LO + b_row + b_chunk_off);
                float* c0 = acc + (2 * p) * 4;
                float* c1 = acc + (2 * p + 1) * 4;
                mma_bf16(c0, ah, bh0, bh1);
                mma_bf16(c0, ah, bl0, bl1);
                mma_bf16(c0, al, bh0, bh1);
                mma_bf16(c1, ah, bh2, bh3);
                mma_bf16(c1, ah, bl2, bl3);
                mma_bf16(c1, al, bh2, bh3);
            }
        }
    }
    __syncthreads();                  // all warps done reading A/B before sY reuse

    // ---- Epilogue: fragments -> sY [128][66] (+bias), then LN/residual ----
    float* sY = (float*)smem;
    {
        int r0 = 16 * warp + (lane >> 2);
        int cb = 2 * (lane & 3);
        #pragma unroll
        for (int j = 0; j < 8; ++j) {
            int col = 8 * j + cb;
            float b0 = sBias[col], b1 = sBias[col + 1];
            *(float2*)&sY[r0 * 66 + col]       = make_float2(acc[4 * j]     + b0, acc[4 * j + 1] + b1);
            *(float2*)&sY[(r0 + 8) * 66 + col] = make_float2(acc[4 * j + 2] + b0, acc[4 * j + 3] + b1);
        }
    }
    __syncthreads();

    if (FINAL) {
        size_t base = (size_t)node0 * FD;
        #pragma unroll
        for (int j = 0; j < 32; ++j) {
            int i = tid + 256 * j;
            int n = i >> 6, f = i & 63;
            outp[base + i] = sY[n * 66 + f] + xres[base + i];
        }
    } else {
        float2 wv = ((const float2*)lnw)[lane];
        float2 bv = ((const float2*)lnb)[lane];
        for (int i = 0; i < 16; ++i) {
            int nl = warp * 16 + i;
            float2 v = *(float2*)&sY[nl * 66 + 2 * lane];
            float s = v.x + v.y;
            #pragma unroll
            for (int o = 16; o; o >>= 1) s += __shfl_xor_sync(0xffffffffu, s, o);
            float mu = s * (1.0f / FD);
            float dx = v.x - mu, dy = v.y - mu;
            float q = dx * dx + dy * dy;
            #pragma unroll
            for (int o = 16; o; o >>= 1) q += __shfl_xor_sync(0xffffffffu, q, o);
            float rs = rsqrtf(q * (1.0f / FD) + LN_EPS);
            float a0 = dx * rs * wv.x + bv.x;
            float a1 = dy * rs * wv.y + bv.y;
            a0 = a0 / (1.0f + __expf(-a0));
            a1 = a1 / (1.0f + __expf(-a1));
            __nv_bfloat16 h0, l0, h1, l1;
            split1(a0, h0, l0);
            split1(a1, h1, l1);
            ((unsigned*)out_hi)[(size_t)(node0 + nl) * 32 + lane] = pack2(h0, h1);
            ((unsigned*)out_lo)[(size_t)(node0 + nl) * 32 + lane] = pack2(l0, l1);
        }
    }
}

// ---------------------------------------------------------------------------
extern "C" void kernel_launch(void* const* d_in, const int* in_sizes, int n_in,
                              void* d_out, int out_size) {
    const float* x    = (const float*)d_in[0];
    const int*   adjc = (const int*)d_in[1];
    const float* ln1w = (const float*)d_in[2];
    const float* ln1b = (const float*)d_in[3];
    const float* W1   = (const float*)d_in[4];
    const float* b1   = (const float*)d_in[5];
    const float* ln2w = (const float*)d_in[6];
    const float* ln2b = (const float*)d_in[7];
    const float* W2   = (const float*)d_in[8];
    const float* b2   = (const float*)d_in[9];
    float*       out  = (float*)d_out;

    (void)in_sizes; (void)n_in; (void)out_size;

    cudaFuncSetAttribute(k_layer<false>,
                         cudaFuncAttributeMaxDynamicSharedMemorySize, SMEM_TOTAL);
    cudaFuncSetAttribute(k_layer<true>,
                         cudaFuncAttributeMaxDynamicSharedMemorySize, SMEM_TOTAL);

    __nv_bfloat16 *hi1, *lo1, *hi2, *lo2;
    cudaGetSymbolAddress((void**)&hi1, g_hi1);
    cudaGetSymbolAddress((void**)&lo1, g_lo1);
    cudaGetSymbolAddress((void**)&hi2, g_hi2);
    cudaGetSymbolAddress((void**)&lo2, g_lo2);

    // K1: split(silu(LN(x)))
    k_ln_silu<<<NN / 8, 256>>>(x, ln1w, ln1b);

    // K2: h2 = split(silu(LN(gather(h1) @ W1 + b1)))
    k_layer<false><<<NN / 128, 256, SMEM_TOTAL>>>(
        hi1, lo1, adjc, W1, b1, ln2w, ln2b, nullptr, hi2, lo2, nullptr);

    // K3: out = gather(h2) @ W2 + b2 + x
    k_layer<true><<<NN / 128, 256, SMEM_TOTAL>>>(
        hi2, lo2, adjc, W2, b2, nullptr, nullptr, x, nullptr, nullptr, out);
}

// round 13
// speedup vs baseline: 1.9521x; 1.1888x over previous
#include <cuda_runtime.h>
#include <cuda_bf16.h>
#include <stdint.h>

// Problem constants
#define NN       196608
#define FD       64
#define NH       9
#define LN_EPS   1e-5f

// Split bf16 activations (hi + lo ~= fp32 to ~16 mantissa bits)
__device__ __align__(256) __nv_bfloat16 g_hi1[(size_t)NN * FD];
__device__ __align__(256) __nv_bfloat16 g_lo1[(size_t)NN * FD];
__device__ __align__(256) __nv_bfloat16 g_hi2[(size_t)NN * FD];
__device__ __align__(256) __nv_bfloat16 g_lo2[(size_t)NN * FD];
// Pre-split, pre-swizzled weights (k-major [f][o], chunk c at (c^(f&7)))
__device__ __align__(256) __nv_bfloat16 g_w1hi[NH * FD * FD];
__device__ __align__(256) __nv_bfloat16 g_w1lo[NH * FD * FD];
__device__ __align__(256) __nv_bfloat16 g_w2hi[NH * FD * FD];
__device__ __align__(256) __nv_bfloat16 g_w2lo[NH * FD * FD];

// ---------------------------------------------------------------------------
// Helpers (sm_80-level features only: ldmatrix + mma.sync + cp.async)
// ---------------------------------------------------------------------------
__device__ __forceinline__ uint32_t smem_u32(const void* p) {
    uint32_t a;
    asm("{ .reg .u64 t; cvta.to.shared.u64 t, %1; cvt.u32.u64 %0, t; }"
        : "=r"(a) : "l"(p));
    return a;
}
__device__ __forceinline__ void cp16(uint32_t dst, const void* src) {
    asm volatile("cp.async.cg.shared.global [%0], [%1], 16;"
                 :: "r"(dst), "l"(src) : "memory");
}
#define CP_COMMIT() asm volatile("cp.async.commit_group;" ::: "memory")

__device__ __forceinline__ void ldsm_x4(uint32_t& r0, uint32_t& r1,
                                        uint32_t& r2, uint32_t& r3, uint32_t a) {
    asm volatile("ldmatrix.sync.aligned.m8n8.x4.shared.b16 {%0,%1,%2,%3}, [%4];"
                 : "=r"(r0), "=r"(r1), "=r"(r2), "=r"(r3) : "r"(a));
}
__device__ __forceinline__ void ldsm_x4_t(uint32_t& r0, uint32_t& r1,
                                          uint32_t& r2, uint32_t& r3, uint32_t a) {
    asm volatile("ldmatrix.sync.aligned.m8n8.x4.trans.shared.b16 {%0,%1,%2,%3}, [%4];"
                 : "=r"(r0), "=r"(r1), "=r"(r2), "=r"(r3) : "r"(a));
}
__device__ __forceinline__ void mma_bf16(float* c, const uint32_t* a,
                                         uint32_t b0, uint32_t b1) {
    asm volatile(
        "mma.sync.aligned.m16n8k16.row.col.f32.bf16.bf16.f32 "
        "{%0,%1,%2,%3}, {%4,%5,%6,%7}, {%8,%9}, {%0,%1,%2,%3};"
        : "+f"(c[0]), "+f"(c[1]), "+f"(c[2]), "+f"(c[3])
        : "r"(a[0]), "r"(a[1]), "r"(a[2]), "r"(a[3]), "r"(b0), "r"(b1));
}

__device__ __forceinline__ unsigned pack2(__nv_bfloat16 a, __nv_bfloat16 b) {
    return (unsigned)__bfloat16_as_ushort(a) | ((unsigned)__bfloat16_as_ushort(b) << 16);
}
__device__ __forceinline__ void split1(float v, __nv_bfloat16& h, __nv_bfloat16& l) {
    h = __float2bfloat16(v);
    l = __float2bfloat16(v - __bfloat162float(h));
}

// ---------------------------------------------------------------------------
// Kernel 0: pre-split both weight tensors into bf16 hi/lo, pre-swizzled.
// 2 layers x 9 heads x 512 chunks; chunk = (f, 16B group of 8 o-values).
// ---------------------------------------------------------------------------
__global__ void k_wsplit(const float* __restrict__ W1,
                         const float* __restrict__ W2) {
    int t = blockIdx.x * 256 + threadIdx.x;
    if (t >= 2 * NH * 512) return;
    int l   = t / (NH * 512);
    int ch  = t % (NH * 512);
    int k   = ch >> 9;
    int rem = ch & 511;
    int f   = rem >> 3, c = rem & 7;

    const float4* wp = (const float4*)((l ? W2 : W1) + (size_t)k * 4096 + f * 64 + c * 8);
    float4 v0 = wp[0], v1 = wp[1];
    float vv[8] = {v0.x, v0.y, v0.z, v0.w, v1.x, v1.y, v1.z, v1.w};
    unsigned rh[4], rl[4];
    #pragma unroll
    for (int j = 0; j < 4; ++j) {
        __nv_bfloat16 h0, l0, h1, l1;
        split1(vv[2 * j], h0, l0);
        split1(vv[2 * j + 1], h1, l1);
        rh[j] = pack2(h0, h1);
        rl[j] = pack2(l0, l1);
    }
    uint32_t off = (uint32_t)k * 8192 + (uint32_t)f * 128 + ((uint32_t)(c ^ (f & 7)) << 4);
    char* dh = (char*)(l ? g_w2hi : g_w1hi);
    char* dl = (char*)(l ? g_w2lo : g_w1lo);
    *(uint4*)(dh + off) = make_uint4(rh[0], rh[1], rh[2], rh[3]);
    *(uint4*)(dl + off) = make_uint4(rl[0], rl[1], rl[2], rl[3]);
}

// ---------------------------------------------------------------------------
// Kernel 1: (hi1, lo1) = split(silu(layernorm(x)))
// ---------------------------------------------------------------------------
__global__ void k_ln_silu(const float* __restrict__ x,
                          const float* __restrict__ lnw,
                          const float* __restrict__ lnb) {
    int row  = (blockIdx.x * blockDim.x + threadIdx.x) >> 5;
    int lane = threadIdx.x & 31;
    if (row >= NN) return;

    float2 v = ((const float2*)(x + (size_t)row * FD))[lane];

    float s = v.x + v.y;
    #pragma unroll
    for (int o = 16; o; o >>= 1) s += __shfl_xor_sync(0xffffffffu, s, o);
    float mu = s * (1.0f / FD);

    float dx = v.x - mu, dy = v.y - mu;
    float q = dx * dx + dy * dy;
    #pragma unroll
    for (int o = 16; o; o >>= 1) q += __shfl_xor_sync(0xffffffffu, q, o);
    float rs = rsqrtf(q * (1.0f / FD) + LN_EPS);

    float2 wv = ((const float2*)lnw)[lane];
    float2 bv = ((const float2*)lnb)[lane];
    float a0 = dx * rs * wv.x + bv.x;
    float a1 = dy * rs * wv.y + bv.y;
    a0 = a0 / (1.0f + __expf(-a0));
    a1 = a1 / (1.0f + __expf(-a1));

    __nv_bfloat16 h0, l0, h1, l1;
    split1(a0, h0, l0);
    split1(a1, h1, l1);
    ((unsigned*)g_hi1)[(size_t)row * 32 + lane] = pack2(h0, h1);
    ((unsigned*)g_lo1)[(size_t)row * 32 + lane] = pack2(l0, l1);
}

// ---------------------------------------------------------------------------
// Layer kernel: warp-level bf16 MMA, 2-term split, cp.async double-buffered.
// Block = 256 threads / 128 nodes; warp w -> nodes [16w, 16w+16).
// Per head: stage(k+1) issued via cp.async before compute(k) -> L2 latency
// fully hidden. B tiles are straight copies of pre-split, pre-swizzled W.
// ---------------------------------------------------------------------------
#define SM_A0     0          // buf0: A_hi 0, A_lo 16384
#define SM_A1     32768      // buf1: A_hi 32768, A_lo 49152
#define SM_B      65536      // buf0: B_hi 65536, B_lo 73728; buf1: +16384
#define SM_IDX    98304      // 1152 ints
#define SM_BIAS   102912     // 64 floats
#define SMEM_TOTAL (102912 + 256)

template <bool FINAL>
__global__ __launch_bounds__(256) void k_layer(
    const __nv_bfloat16* __restrict__ hin_hi,
    const __nv_bfloat16* __restrict__ hin_lo,
    const int* __restrict__ adjc,
    const __nv_bfloat16* __restrict__ whi,   // pre-split, pre-swizzled
    const __nv_bfloat16* __restrict__ wlo,
    const float* __restrict__ bias,
    const float* __restrict__ lnw,
    const float* __restrict__ lnb,
    const float* __restrict__ xres,
    __nv_bfloat16* __restrict__ out_hi,
    __nv_bfloat16* __restrict__ out_lo,
    float* __restrict__ outp)
{
    extern __shared__ char smem[];
    const uint32_t sb = smem_u32(smem);
    const int tid  = threadIdx.x;
    const int lane = tid & 31;
    const int warp = tid >> 5;
    const int node0 = blockIdx.x * 128;

    int*   sIdx  = (int*)(smem + SM_IDX);
    float* sBias = (float*)(smem + SM_BIAS);

    if (tid < 64) sBias[tid] = bias[tid];
    for (int i = tid; i < 128 * NH; i += 256) {
        int v = adjc[(size_t)node0 * NH + i];
        v = (v < 0) ? 0 : ((v >= NN) ? NN - 1 : v);
        sIdx[i] = v;
    }
    __syncthreads();

    float acc[32];
    #pragma unroll
    for (int i = 0; i < 32; ++i) acc[i] = 0.0f;

    const int gnode = tid & 127;
    const int gsel  = tid >> 7;
    const int l7    = lane & 7;
    const int l15   = lane & 15;
    const int hi16  = lane >> 4;
    const int g8    = lane >> 3;

    const uint32_t a_row_off  = (uint32_t)(16 * warp + l15) * 128;
    const uint32_t b_krow_off = (uint32_t)(8 * (g8 & 1) + l7) * 128;
    const int b_cg = g8 >> 1;

    // Stage issuer: head k into buffer buf (all via cp.async, one commit group)
    auto issue_stage = [&](int k, int buf) {
        // A gather: this thread copies one 128B row (hi or lo tile)
        int src = sIdx[gnode * NH + k];
        const char* row = (const char*)((gsel ? hin_lo : hin_hi) + (size_t)src * FD);
        uint32_t dstA = sb + (buf ? SM_A1 : SM_A0) + (uint32_t)gsel * 16384
                      + (uint32_t)gnode * 128;
        #pragma unroll
        for (int c = 0; c < 8; ++c)
            cp16(dstA + ((uint32_t)(c ^ (gnode & 7)) << 4), row + c * 16);
        // B copy: 1024 16B chunks over 256 threads (pre-swizzled source)
        const char* bh = (const char*)whi + (size_t)k * 8192;
        const char* bl = (const char*)wlo + (size_t)k * 8192;
        uint32_t dstB = sb + SM_B + (uint32_t)buf * 16384;
        #pragma unroll
        for (int i = 0; i < 4; ++i) {
            int idx = tid + 256 * i;
            int sel = idx >> 9;
            uint32_t off = (uint32_t)(idx & 511) << 4;
            cp16(dstB + (uint32_t)sel * 8192 + off, (sel ? bl : bh) + off);
        }
        CP_COMMIT();
    };

    issue_stage(0, 0);

    for (int k = 0; k < NH; ++k) {
        const int buf = k & 1;
        if (k + 1 < NH) issue_stage(k + 1, buf ^ 1);
        if (k + 1 < NH) asm volatile("cp.async.wait_group 1;" ::: "memory");
        else            asm volatile("cp.async.wait_group 0;" ::: "memory");
        __syncthreads();                       // stage(k) visible to all warps

        const uint32_t aBase = sb + (buf ? SM_A1 : SM_A0);
        const uint32_t bBase = sb + SM_B + (uint32_t)buf * 16384;

        #pragma unroll
        for (int ks = 0; ks < 4; ++ks) {
            uint32_t a_chunk_off = (uint32_t)(((2 * ks + hi16) ^ l7) << 4);
            uint32_t ah[4], al[4];
            ldsm_x4(ah[0], ah[1], ah[2], ah[3], aBase + a_row_off + a_chunk_off);
            ldsm_x4(al[0], al[1], al[2], al[3], aBase + 16384 + a_row_off + a_chunk_off);

            uint32_t b_row = (uint32_t)(16 * ks) * 128 + b_krow_off;
            #pragma unroll
            for (int p = 0; p < 4; ++p) {
                uint32_t b_chunk_off = (uint32_t)(((2 * p + b_cg) ^ l7) << 4);
                uint32_t bh0, bh1, bh2, bh3, bl0, bl1, bl2, bl3;
                ldsm_x4_t(bh0, bh1, bh2, bh3, bBase + b_row + b_chunk_off);
                ldsm_x4_t(bl0, bl1, bl2, bl3, bBase + 8192 + b_row + b_chunk_off);
                float* c0 = acc + (2 * p) * 4;
                float* c1 = acc + (2 * p + 1) * 4;
                mma_bf16(c0, ah, bh0, bh1);
                mma_bf16(c0, ah, bl0, bl1);
                mma_bf16(c0, al, bh0, bh1);
                mma_bf16(c1, ah, bh2, bh3);
                mma_bf16(c1, ah, bl2, bl3);
                mma_bf16(c1, al, bh2, bh3);
            }
        }
        __syncthreads();                       // compute(k) done before buf reuse
    }

    // ---- Epilogue: fragments -> sY [128][66] (+bias), then LN/residual ----
    float* sY = (float*)smem;
    {
        int r0 = 16 * warp + (lane >> 2);
        int cb = 2 * (lane & 3);
        #pragma unroll
        for (int j = 0; j < 8; ++j) {
            int col = 8 * j + cb;
            float b0 = sBias[col], b1 = sBias[col + 1];
            *(float2*)&sY[r0 * 66 + col]       = make_float2(acc[4 * j]     + b0, acc[4 * j + 1] + b1);
            *(float2*)&sY[(r0 + 8) * 66 + col] = make_float2(acc[4 * j + 2] + b0, acc[4 * j + 3] + b1);
        }
    }
    __syncthreads();

    if (FINAL) {
        size_t base = (size_t)node0 * FD;
        #pragma unroll
        for (int j = 0; j < 32; ++j) {
            int i = tid + 256 * j;
            int n = i >> 6, f = i & 63;
            outp[base + i] = sY[n * 66 + f] + xres[base + i];
        }
    } else {
        float2 wv = ((const float2*)lnw)[lane];
        float2 bv = ((const float2*)lnb)[lane];
        for (int i = 0; i < 16; ++i) {
            int nl = warp * 16 + i;
            float2 v = *(float2*)&sY[nl * 66 + 2 * lane];
            float s = v.x + v.y;
            #pragma unroll
            for (int o = 16; o; o >>= 1) s += __shfl_xor_sync(0xffffffffu, s, o);
            float mu = s * (1.0f / FD);
            float dx = v.x - mu, dy = v.y - mu;
            float q = dx * dx + dy * dy;
            #pragma unroll
            for (int o = 16; o; o >>= 1) q += __shfl_xor_sync(0xffffffffu, q, o);
            float rs = rsqrtf(q * (1.0f / FD) + LN_EPS);
            float a0 = dx * rs * wv.x + bv.x;
            float a1 = dy * rs * wv.y + bv.y;
            a0 = a0 / (1.0f + __expf(-a0));
            a1 = a1 / (1.0f + __expf(-a1));
            __nv_bfloat16 h0, l0, h1, l1;
            split1(a0, h0, l0);
            split1(a1, h1, l1);
            ((unsigned*)out_hi)[(size_t)(node0 + nl) * 32 + lane] = pack2(h0, h1);
            ((unsigned*)out_lo)[(size_t)(node0 + nl) * 32 + lane] = pack2(l0, l1);
        }
    }
}

// ---------------------------------------------------------------------------
extern "C" void kernel_launch(void* const* d_in, const int* in_sizes, int n_in,
                              void* d_out, int out_size) {
    const float* x    = (const float*)d_in[0];
    const int*   adjc = (const int*)d_in[1];
    const float* ln1w = (const float*)d_in[2];
    const float* ln1b = (const float*)d_in[3];
    const float* W1   = (const float*)d_in[4];
    const float* b1   = (const float*)d_in[5];
    const float* ln2w = (const float*)d_in[6];
    const float* ln2b = (const float*)d_in[7];
    const float* W2   = (const float*)d_in[8];
    const float* b2   = (const float*)d_in[9];
    float*       out  = (float*)d_out;

    (void)in_sizes; (void)n_in; (void)out_size;

    cudaFuncSetAttribute(k_layer<false>,
                         cudaFuncAttributeMaxDynamicSharedMemorySize, SMEM_TOTAL);
    cudaFuncSetAttribute(k_layer<true>,
                         cudaFuncAttributeMaxDynamicSharedMemorySize, SMEM_TOTAL);

    __nv_bfloat16 *hi1, *lo1, *hi2, *lo2, *w1h, *w1l, *w2h, *w2l;
    cudaGetSymbolAddress((void**)&hi1, g_hi1);
    cudaGetSymbolAddress((void**)&lo1, g_lo1);
    cudaGetSymbolAddress((void**)&hi2, g_hi2);
    cudaGetSymbolAddress((void**)&lo2, g_lo2);
    cudaGetSymbolAddress((void**)&w1h, g_w1hi);
    cudaGetSymbolAddress((void**)&w1l, g_w1lo);
    cudaGetSymbolAddress((void**)&w2h, g_w2hi);
    cudaGetSymbolAddress((void**)&w2l, g_w2lo);

    // K0: pre-split weights (both layers)
    k_wsplit<<<(2 * NH * 512 + 255) / 256, 256>>>(W1, W2);
    // K1: split(silu(LN(x)))
    k_ln_silu<<<NN / 8, 256>>>(x, ln1w, ln1b);
    // K2: h2 = split(silu(LN(gather(h1) @ W1 + b1)))
    k_layer<false><<<NN / 128, 256, SMEM_TOTAL>>>(
        hi1, lo1, adjc, w1h, w1l, b1, ln2w, ln2b, nullptr, hi2, lo2, nullptr);
    // K3: out = gather(h2) @ W2 + b2 + x
    k_layer<true><<<NN / 128, 256, SMEM_TOTAL>>>(
        hi2, lo2, adjc, w2h, w2l, b2, nullptr, nullptr, x, nullptr, nullptr, out);
}

// round 14
// speedup vs baseline: 2.0011x; 1.0251x over previous
#include <cuda_runtime.h>
#include <cuda_bf16.h>
#include <stdint.h>

// Problem constants
#define NN       196608
#define FD       64
#define NH       9
#define LN_EPS   1e-5f

// Split bf16 activations (hi + lo ~= fp32 to ~16 mantissa bits)
__device__ __align__(256) __nv_bfloat16 g_hi1[(size_t)NN * FD];
__device__ __align__(256) __nv_bfloat16 g_lo1[(size_t)NN * FD];
__device__ __align__(256) __nv_bfloat16 g_hi2[(size_t)NN * FD];
__device__ __align__(256) __nv_bfloat16 g_lo2[(size_t)NN * FD];
// Pre-split, pre-swizzled weights (k-major [f][o], chunk c at (c^(f&7)))
__device__ __align__(256) __nv_bfloat16 g_w1hi[NH * FD * FD];
__device__ __align__(256) __nv_bfloat16 g_w1lo[NH * FD * FD];
__device__ __align__(256) __nv_bfloat16 g_w2hi[NH * FD * FD];
__device__ __align__(256) __nv_bfloat16 g_w2lo[NH * FD * FD];

// ---------------------------------------------------------------------------
// Helpers (sm_80-level features only: ldmatrix + mma.sync + cp.async)
// ---------------------------------------------------------------------------
__device__ __forceinline__ uint32_t smem_u32(const void* p) {
    uint32_t a;
    asm("{ .reg .u64 t; cvta.to.shared.u64 t, %1; cvt.u32.u64 %0, t; }"
        : "=r"(a) : "l"(p));
    return a;
}
__device__ __forceinline__ void cp16(uint32_t dst, const void* src) {
    asm volatile("cp.async.cg.shared.global [%0], [%1], 16;"
                 :: "r"(dst), "l"(src) : "memory");
}
#define CP_COMMIT() asm volatile("cp.async.commit_group;" ::: "memory")

__device__ __forceinline__ void ldsm_x4(uint32_t& r0, uint32_t& r1,
                                        uint32_t& r2, uint32_t& r3, uint32_t a) {
    asm volatile("ldmatrix.sync.aligned.m8n8.x4.shared.b16 {%0,%1,%2,%3}, [%4];"
                 : "=r"(r0), "=r"(r1), "=r"(r2), "=r"(r3) : "r"(a));
}
__device__ __forceinline__ void ldsm_x4_t(uint32_t& r0, uint32_t& r1,
                                          uint32_t& r2, uint32_t& r3, uint32_t a) {
    asm volatile("ldmatrix.sync.aligned.m8n8.x4.trans.shared.b16 {%0,%1,%2,%3}, [%4];"
                 : "=r"(r0), "=r"(r1), "=r"(r2), "=r"(r3) : "r"(a));
}
__device__ __forceinline__ void mma_bf16(float* c, const uint32_t* a,
                                         uint32_t b0, uint32_t b1) {
    asm volatile(
        "mma.sync.aligned.m16n8k16.row.col.f32.bf16.bf16.f32 "
        "{%0,%1,%2,%3}, {%4,%5,%6,%7}, {%8,%9}, {%0,%1,%2,%3};"
        : "+f"(c[0]), "+f"(c[1]), "+f"(c[2]), "+f"(c[3])
        : "r"(a[0]), "r"(a[1]), "r"(a[2]), "r"(a[3]), "r"(b0), "r"(b1));
}

__device__ __forceinline__ unsigned pack2(__nv_bfloat16 a, __nv_bfloat16 b) {
    return (unsigned)__bfloat16_as_ushort(a) | ((unsigned)__bfloat16_as_ushort(b) << 16);
}
__device__ __forceinline__ void split1(float v, __nv_bfloat16& h, __nv_bfloat16& l) {
    h = __float2bfloat16(v);
    l = __float2bfloat16(v - __bfloat162float(h));
}

// ---------------------------------------------------------------------------
// Kernel 0: pre-split both weight tensors into bf16 hi/lo, pre-swizzled.
// ---------------------------------------------------------------------------
__global__ void k_wsplit(const float* __restrict__ W1,
                         const float* __restrict__ W2) {
    int t = blockIdx.x * 256 + threadIdx.x;
    if (t >= 2 * NH * 512) return;
    int l   = t / (NH * 512);
    int ch  = t % (NH * 512);
    int k   = ch >> 9;
    int rem = ch & 511;
    int f   = rem >> 3, c = rem & 7;

    const float4* wp = (const float4*)((l ? W2 : W1) + (size_t)k * 4096 + f * 64 + c * 8);
    float4 v0 = wp[0], v1 = wp[1];
    float vv[8] = {v0.x, v0.y, v0.z, v0.w, v1.x, v1.y, v1.z, v1.w};
    unsigned rh[4], rl[4];
    #pragma unroll
    for (int j = 0; j < 4; ++j) {
        __nv_bfloat16 h0, l0, h1, l1;
        split1(vv[2 * j], h0, l0);
        split1(vv[2 * j + 1], h1, l1);
        rh[j] = pack2(h0, h1);
        rl[j] = pack2(l0, l1);
    }
    uint32_t off = (uint32_t)k * 8192 + (uint32_t)f * 128 + ((uint32_t)(c ^ (f & 7)) << 4);
    char* dh = (char*)(l ? g_w2hi : g_w1hi);
    char* dl = (char*)(l ? g_w2lo : g_w1lo);
    *(uint4*)(dh + off) = make_uint4(rh[0], rh[1], rh[2], rh[3]);
    *(uint4*)(dl + off) = make_uint4(rl[0], rl[1], rl[2], rl[3]);
}

// ---------------------------------------------------------------------------
// Kernel 1: (hi1, lo1) = split(silu(layernorm(x)))
// ---------------------------------------------------------------------------
__global__ void k_ln_silu(const float* __restrict__ x,
                          const float* __restrict__ lnw,
                          const float* __restrict__ lnb) {
    int row  = (blockIdx.x * blockDim.x + threadIdx.x) >> 5;
    int lane = threadIdx.x & 31;
    if (row >= NN) return;

    float2 v = ((const float2*)(x + (size_t)row * FD))[lane];

    float s = v.x + v.y;
    #pragma unroll
    for (int o = 16; o; o >>= 1) s += __shfl_xor_sync(0xffffffffu, s, o);
    float mu = s * (1.0f / FD);

    float dx = v.x - mu, dy = v.y - mu;
    float q = dx * dx + dy * dy;
    #pragma unroll
    for (int o = 16; o; o >>= 1) q += __shfl_xor_sync(0xffffffffu, q, o);
    float rs = rsqrtf(q * (1.0f / FD) + LN_EPS);

    float2 wv = ((const float2*)lnw)[lane];
    float2 bv = ((const float2*)lnb)[lane];
    float a0 = dx * rs * wv.x + bv.x;
    float a1 = dy * rs * wv.y + bv.y;
    a0 = a0 / (1.0f + __expf(-a0));
    a1 = a1 / (1.0f + __expf(-a1));

    __nv_bfloat16 h0, l0, h1, l1;
    split1(a0, h0, l0);
    split1(a1, h1, l1);
    ((unsigned*)g_hi1)[(size_t)row * 32 + lane] = pack2(h0, h1);
    ((unsigned*)g_lo1)[(size_t)row * 32 + lane] = pack2(l0, l1);
}

// ---------------------------------------------------------------------------
// Layer kernel: warp-level bf16 MMA, 2-term split, cp.async double-buffered.
// R14 change: term-major MMA ordering — per k-step, preload ALL B fragments,
// then sweep each split-term across all 4 n-pairs. Consecutive MMAs hit 8
// distinct accumulators (reuse distance 1 -> 8), hiding HMMA latency.
// Per-accumulator term order unchanged -> numerics bit-identical to R13.
// ---------------------------------------------------------------------------
#define SM_A0     0          // buf0: A_hi 0, A_lo 16384
#define SM_A1     32768      // buf1: A_hi 32768, A_lo 49152
#define SM_B      65536      // buf0: B_hi 65536, B_lo 73728; buf1: +16384
#define SM_IDX    98304      // 1152 ints
#define SM_BIAS   102912     // 64 floats
#define SMEM_TOTAL (102912 + 256)

template <bool FINAL>
__global__ __launch_bounds__(256) void k_layer(
    const __nv_bfloat16* __restrict__ hin_hi,
    const __nv_bfloat16* __restrict__ hin_lo,
    const int* __restrict__ adjc,
    const __nv_bfloat16* __restrict__ whi,   // pre-split, pre-swizzled
    const __nv_bfloat16* __restrict__ wlo,
    const float* __restrict__ bias,
    const float* __restrict__ lnw,
    const float* __restrict__ lnb,
    const float* __restrict__ xres,
    __nv_bfloat16* __restrict__ out_hi,
    __nv_bfloat16* __restrict__ out_lo,
    float* __restrict__ outp)
{
    extern __shared__ char smem[];
    const uint32_t sb = smem_u32(smem);
    const int tid  = threadIdx.x;
    const int lane = tid & 31;
    const int warp = tid >> 5;
    const int node0 = blockIdx.x * 128;

    int*   sIdx  = (int*)(smem + SM_IDX);
    float* sBias = (float*)(smem + SM_BIAS);

    if (tid < 64) sBias[tid] = bias[tid];
    for (int i = tid; i < 128 * NH; i += 256) {
        int v = adjc[(size_t)node0 * NH + i];
        v = (v < 0) ? 0 : ((v >= NN) ? NN - 1 : v);
        sIdx[i] = v;
    }
    __syncthreads();

    float acc[32];
    #pragma unroll
    for (int i = 0; i < 32; ++i) acc[i] = 0.0f;

    const int gnode = tid & 127;
    const int gsel  = tid >> 7;
    const int l7    = lane & 7;
    const int l15   = lane & 15;
    const int hi16  = lane >> 4;
    const int g8    = lane >> 3;

    const uint32_t a_row_off  = (uint32_t)(16 * warp + l15) * 128;
    const uint32_t b_krow_off = (uint32_t)(8 * (g8 & 1) + l7) * 128;
    const int b_cg = g8 >> 1;

    // Stage issuer: head k into buffer buf (all via cp.async, one commit group)
    auto issue_stage = [&](int k, int buf) {
        int src = sIdx[gnode * NH + k];
        const char* row = (const char*)((gsel ? hin_lo : hin_hi) + (size_t)src * FD);
        uint32_t dstA = sb + (buf ? SM_A1 : SM_A0) + (uint32_t)gsel * 16384
                      + (uint32_t)gnode * 128;
        #pragma unroll
        for (int c = 0; c < 8; ++c)
            cp16(dstA + ((uint32_t)(c ^ (gnode & 7)) << 4), row + c * 16);
        const char* bh = (const char*)whi + (size_t)k * 8192;
        const char* bl = (const char*)wlo + (size_t)k * 8192;
        uint32_t dstB = sb + SM_B + (uint32_t)buf * 16384;
        #pragma unroll
        for (int i = 0; i < 4; ++i) {
            int idx = tid + 256 * i;
            int sel = idx >> 9;
            uint32_t off = (uint32_t)(idx & 511) << 4;
            cp16(dstB + (uint32_t)sel * 8192 + off, (sel ? bl : bh) + off);
        }
        CP_COMMIT();
    };

    issue_stage(0, 0);

    for (int k = 0; k < NH; ++k) {
        const int buf = k & 1;
        if (k + 1 < NH) issue_stage(k + 1, buf ^ 1);
        if (k + 1 < NH) asm volatile("cp.async.wait_group 1;" ::: "memory");
        else            asm volatile("cp.async.wait_group 0;" ::: "memory");
        __syncthreads();                       // stage(k) visible to all warps

        const uint32_t aBase = sb + (buf ? SM_A1 : SM_A0);
        const uint32_t bBase = sb + SM_B + (uint32_t)buf * 16384;

        #pragma unroll
        for (int ks = 0; ks < 4; ++ks) {
            uint32_t a_chunk_off = (uint32_t)(((2 * ks + hi16) ^ l7) << 4);
            uint32_t ah[4], al[4];
            ldsm_x4(ah[0], ah[1], ah[2], ah[3], aBase + a_row_off + a_chunk_off);
            ldsm_x4(al[0], al[1], al[2], al[3], aBase + 16384 + a_row_off + a_chunk_off);

            // Preload ALL B fragments for this k-step (8 independent ldsm)
            uint32_t b_row = (uint32_t)(16 * ks) * 128 + b_krow_off;
            uint32_t bh[16], bl[16];
            #pragma unroll
            for (int p = 0; p < 4; ++p) {
                uint32_t b_chunk_off = (uint32_t)(((2 * p + b_cg) ^ l7) << 4);
                ldsm_x4_t(bh[4*p], bh[4*p+1], bh[4*p+2], bh[4*p+3],
                          bBase + b_row + b_chunk_off);
                ldsm_x4_t(bl[4*p], bl[4*p+1], bl[4*p+2], bl[4*p+3],
                          bBase + 8192 + b_row + b_chunk_off);
            }
            // Term-major sweeps: 8 distinct accumulators between acc reuses
            #pragma unroll
            for (int p = 0; p < 4; ++p) {
                mma_bf16(acc + 8*p,     ah, bh[4*p],   bh[4*p+1]);
                mma_bf16(acc + 8*p + 4, ah, bh[4*p+2], bh[4*p+3]);
            }
            #pragma unroll
            for (int p = 0; p < 4; ++p) {
                mma_bf16(acc + 8*p,     ah, bl[4*p],   bl[4*p+1]);
                mma_bf16(acc + 8*p + 4, ah, bl[4*p+2], bl[4*p+3]);
            }
            #pragma unroll
            for (int p = 0; p < 4; ++p) {
                mma_bf16(acc + 8*p,     al, bh[4*p],   bh[4*p+1]);
                mma_bf16(acc + 8*p + 4, al, bh[4*p+2], bh[4*p+3]);
            }
        }
        __syncthreads();                       // compute(k) done before buf reuse
    }

    // ---- Epilogue: fragments -> sY [128][66] (+bias), then LN/residual ----
    float* sY = (float*)smem;
    {
        int r0 = 16 * warp + (lane >> 2);
        int cb = 2 * (lane & 3);
        #pragma unroll
        for (int j = 0; j < 8; ++j) {
            int col = 8 * j + cb;
            float b0 = sBias[col], b1 = sBias[col + 1];
            *(float2*)&sY[r0 * 66 + col]       = make_float2(acc[4 * j]     + b0, acc[4 * j + 1] + b1);
            *(float2*)&sY[(r0 + 8) * 66 + col] = make_float2(acc[4 * j + 2] + b0, acc[4 * j + 3] + b1);
        }
    }
    __syncthreads();

    if (FINAL) {
        size_t base = (size_t)node0 * FD;
        #pragma unroll
        for (int j = 0; j < 32; ++j) {
            int i = tid + 256 * j;
            int n = i >> 6, f = i & 63;
            outp[base + i] = sY[n * 66 + f] + xres[base + i];
        }
    } else {
        float2 wv = ((const float2*)lnw)[lane];
        float2 bv = ((const float2*)lnb)[lane];
        for (int i = 0; i < 16; ++i) {
            int nl = warp * 16 + i;
            float2 v = *(float2*)&sY[nl * 66 + 2 * lane];
            float s = v.x + v.y;
            #pragma unroll
            for (int o = 16; o; o >>= 1) s += __shfl_xor_sync(0xffffffffu, s, o);
            float mu = s * (1.0f / FD);
            float dx = v.x - mu, dy = v.y - mu;
            float q = dx * dx + dy * dy;
            #pragma unroll
            for (int o = 16; o; o >>= 1) q += __shfl_xor_sync(0xffffffffu, q, o);
            float rs = rsqrtf(q * (1.0f / FD) + LN_EPS);
            float a0 = dx * rs * wv.x + bv.x;
            float a1 = dy * rs * wv.y + bv.y;
            a0 = a0 / (1.0f + __expf(-a0));
            a1 = a1 / (1.0f + __expf(-a1));
            __nv_bfloat16 h0, l0, h1, l1;
            split1(a0, h0, l0);
            split1(a1, h1, l1);
            ((unsigned*)out_hi)[(size_t)(node0 + nl) * 32 + lane] = pack2(h0, h1);
            ((unsigned*)out_lo)[(size_t)(node0 + nl) * 32 + lane] = pack2(l0, l1);
        }
    }
}

// ---------------------------------------------------------------------------
extern "C" void kernel_launch(void* const* d_in, const int* in_sizes, int n_in,
                              void* d_out, int out_size) {
    const float* x    = (const float*)d_in[0];
    const int*   adjc = (const int*)d_in[1];
    const float* ln1w = (const float*)d_in[2];
    const float* ln1b = (const float*)d_in[3];
    const float* W1   = (const float*)d_in[4];
    const float* b1   = (const float*)d_in[5];
    const float* ln2w = (const float*)d_in[6];
    const float* ln2b = (const float*)d_in[7];
    const float* W2   = (const float*)d_in[8];
    const float* b2   = (const float*)d_in[9];
    float*       out  = (float*)d_out;

    (void)in_sizes; (void)n_in; (void)out_size;

    cudaFuncSetAttribute(k_layer<false>,
                         cudaFuncAttributeMaxDynamicSharedMemorySize, SMEM_TOTAL);
    cudaFuncSetAttribute(k_layer<true>,
                         cudaFuncAttributeMaxDynamicSharedMemorySize, SMEM_TOTAL);

    __nv_bfloat16 *hi1, *lo1, *hi2, *lo2, *w1h, *w1l, *w2h, *w2l;
    cudaGetSymbolAddress((void**)&hi1, g_hi1);
    cudaGetSymbolAddress((void**)&lo1, g_lo1);
    cudaGetSymbolAddress((void**)&hi2, g_hi2);
    cudaGetSymbolAddress((void**)&lo2, g_lo2);
    cudaGetSymbolAddress((void**)&w1h, g_w1hi);
    cudaGetSymbolAddress((void**)&w1l, g_w1lo);
    cudaGetSymbolAddress((void**)&w2h, g_w2hi);
    cudaGetSymbolAddress((void**)&w2l, g_w2lo);

    // K0: pre-split weights (both layers)
    k_wsplit<<<(2 * NH * 512 + 255) / 256, 256>>>(W1, W2);
    // K1: split(silu(LN(x)))
    k_ln_silu<<<NN / 8, 256>>>(x, ln1w, ln1b);
    // K2: h2 = split(silu(LN(gather(h1) @ W1 + b1)))
    k_layer<false><<<NN / 128, 256, SMEM_TOTAL>>>(
        hi1, lo1, adjc, w1h, w1l, b1, ln2w, ln2b, nullptr, hi2, lo2, nullptr);
    // K3: out = gather(h2) @ W2 + b2 + x
    k_layer<true><<<NN / 128, 256, SMEM_TOTAL>>>(
        hi2, lo2, adjc, w2h, w2l, b2, nullptr, nullptr, x, nullptr, nullptr, out);
}